// round 3
// baseline (speedup 1.0000x reference)
#include <cuda_runtime.h>
#include <math.h>

#define H 4096
#define HS 64
#define NH 64
#define TM 64
#define TD 128

// ---------------- scratch (device globals; no allocation allowed) ----------------
__device__ float g_xn[H];
__device__ float g_sx[H];
__device__ float g_xxx[H];
__device__ float g_maa_part[16][5 * TM];      // split-K partials for W_maa1
__device__ float g_m[5][H];                   // mw, mk, mv, mr, mg
__device__ float g_part[4 * 64 * H];          // split-K partials for Wr/Wk/Wv/Wg (4 MB)
__device__ float g_wd1_part[16][TD];
__device__ float g_rkvg[4][H];                // r, k, v, g(silu applied)
__device__ float g_ddpre[TD];
__device__ float g_td[H];
__device__ float g_gx[H];                     // (instnorm(out)*w+b) * gate
__device__ float g_wo_part[64 * H];

// ---------------- K1: LN1 + token shift prep ----------------
__global__ void k1_ln_prep(const float* __restrict__ x,
                           const float* __restrict__ s1,
                           const float* __restrict__ ln1_w,
                           const float* __restrict__ ln1_b,
                           const float* __restrict__ tmx,
                           float* __restrict__ d_out) {
    __shared__ float s_sum[1024];
    __shared__ float s_sq[1024];
    int t = threadIdx.x;
    float4 xv = reinterpret_cast<const float4*>(x)[t];
    float lsum = xv.x + xv.y + xv.z + xv.w;
    float lsq = xv.x * xv.x + xv.y * xv.y + xv.z * xv.z + xv.w * xv.w;
    s_sum[t] = lsum; s_sq[t] = lsq;
    __syncthreads();
    for (int s = 512; s > 0; s >>= 1) {
        if (t < s) { s_sum[t] += s_sum[t + s]; s_sq[t] += s_sq[t + s]; }
        __syncthreads();
    }
    float mean = s_sum[0] * (1.0f / H);
    float var = s_sq[0] * (1.0f / H) - mean * mean;
    float rs = rsqrtf(var + 1e-5f);
    float xe[4] = {xv.x, xv.y, xv.z, xv.w};
#pragma unroll
    for (int q = 0; q < 4; q++) {
        int i = t * 4 + q;
        float xn = (xe[q] - mean) * rs * ln1_w[i] + ln1_b[i];
        float sx = s1[i] - xn;
        g_xn[i] = xn;
        g_sx[i] = sx;
        g_xxx[i] = xn + sx * tmx[i];
        d_out[H + i] = xn;   // state1_out
    }
}

// ---------------- K2: W_maa1 GEMV partials (4096 x 320) ----------------
__global__ void k2_maa1_part(const float* __restrict__ Wmaa1) {
    __shared__ float sv[256];
    int c = blockIdx.x;           // 16 chunks of 256 rows
    int t = threadIdx.x;          // 320 threads
    if (t < 256) sv[t] = g_xxx[c * 256 + t];
    __syncthreads();
    float acc = 0.f;
#pragma unroll 8
    for (int i = 0; i < 256; i++)
        acc += sv[i] * Wmaa1[(size_t)(c * 256 + i) * 320 + t];
    g_maa_part[c][t] = acc;
}

// ---------------- K3: mix = tanh(reduce), m = xn + sx*(mix@W_maa2 + maa) ----------------
__global__ void k3_mix(const float* __restrict__ Wmaa2,
                       const float* __restrict__ maa_w,
                       const float* __restrict__ maa_k,
                       const float* __restrict__ maa_v,
                       const float* __restrict__ maa_r,
                       const float* __restrict__ maa_g) {
    __shared__ float mixs[TM];
    int s = blockIdx.y;
    int t = threadIdx.x;
    if (t < TM) {
        float a = 0.f;
#pragma unroll
        for (int c = 0; c < 16; c++) a += g_maa_part[c][s * TM + t];
        mixs[t] = tanhf(a);
    }
    __syncthreads();
    int h = blockIdx.x * 256 + t;
    float acc = 0.f;
#pragma unroll 8
    for (int e = 0; e < TM; e++)
        acc += mixs[e] * Wmaa2[(size_t)(s * TM + e) * H + h];
    const float* maa = (s == 0) ? maa_w : (s == 1) ? maa_k : (s == 2) ? maa_v
                      : (s == 3) ? maa_r : maa_g;
    g_m[s][h] = g_xn[h] + g_sx[h] * (acc + maa[h]);
}

// ---------------- K4: big split-K GEMV partials for Wr/Wk/Wv/Wg ----------------
// grid: (64 splits, 4 mats, 4 col-chunks), 256 threads.
// Each block: rows [split*64, split*64+64), float4 cols [cc*256, cc*256+256).
__global__ void k4_big_part(const float* __restrict__ Wr,
                            const float* __restrict__ Wk,
                            const float* __restrict__ Wv,
                            const float* __restrict__ Wg) {
    __shared__ float sv[64];
    int split = blockIdx.x;     // 64 splits of 64 rows
    int mat = blockIdx.y;       // 0:r 1:k 2:v 3:g
    int cc = blockIdx.z;        // 4 column chunks of 256 float4s
    int t = threadIdx.x;        // 256 threads
    const float* vec = (mat == 0) ? g_m[3] : (mat == 1) ? g_m[1]
                      : (mat == 2) ? g_m[2] : g_m[4];
    const float* W = (mat == 0) ? Wr : (mat == 1) ? Wk : (mat == 2) ? Wv : Wg;
    if (t < 64) sv[t] = vec[split * 64 + t];
    __syncthreads();
    const float4* W4 = reinterpret_cast<const float4*>(W);
    int col = cc * 256 + t;     // float4 column index, 0..1023
    float4 acc = make_float4(0.f, 0.f, 0.f, 0.f);
#pragma unroll 4
    for (int i = 0; i < 64; i++) {
        float m = sv[i];
        float4 w = W4[(size_t)(split * 64 + i) * 1024 + col];
        acc.x += m * w.x; acc.y += m * w.y; acc.z += m * w.z; acc.w += m * w.w;
    }
    reinterpret_cast<float4*>(&g_part[(size_t)(mat * 64 + split) * H])[col] = acc;
}

// ---------------- K4b: Wd1 partials (4096 x 128) ----------------
__global__ void k4b_wd1_part(const float* __restrict__ Wd1) {
    __shared__ float sv[256];
    int c = blockIdx.x;          // 16 chunks of 256 rows
    int t = threadIdx.x;         // 128 threads
    sv[t] = g_m[0][c * 256 + t];
    sv[t + 128] = g_m[0][c * 256 + 128 + t];
    __syncthreads();
    float acc = 0.f;
#pragma unroll 8
    for (int i = 0; i < 256; i++)
        acc += sv[i] * Wd1[(size_t)(c * 256 + i) * TD + t];
    g_wd1_part[c][t] = acc;
}

// ---------------- K5: reduce big partials (+silu on gate) ----------------
__global__ void k5_reduce(void) {
    int idx = blockIdx.x * 256 + threadIdx.x;   // 64 blocks -> 16384
    int mat = idx >> 12;
    int j = idx & (H - 1);
    float a = 0.f;
#pragma unroll 8
    for (int s = 0; s < 64; s++)
        a += g_part[(size_t)(mat * 64 + s) * H + j];
    if (mat == 3) a = a / (1.0f + expf(-a));   // silu
    g_rkvg[mat][j] = a;
}

// ---------------- K5b: reduce Wd1 partials + tanh ----------------
__global__ void k5b_ddpre(void) {
    int t = threadIdx.x;  // 128
    float a = 0.f;
#pragma unroll
    for (int c = 0; c < 16; c++) a += g_wd1_part[c][t];
    g_ddpre[t] = tanhf(a);
}

// ---------------- K6: dd@Wd2, td = exp(-exp(time_decay + dd)) ----------------
__global__ void k6_decay(const float* __restrict__ Wd2,
                         const float* __restrict__ time_decay) {
    __shared__ float sdd[TD];
    int t = threadIdx.x;
    if (t < TD) sdd[t] = g_ddpre[t];
    __syncthreads();
    int j = blockIdx.x * 256 + t;
    float acc = 0.f;
#pragma unroll 8
    for (int e = 0; e < TD; e++)
        acc += sdd[e] * Wd2[(size_t)e * H + j];
    g_td[j] = expf(-expf(time_decay[j] + acc));
}

// ---------------- K7: per-head attention + state update + instnorm + gate ----------------
__global__ void k7_heads(const float* __restrict__ state2,
                         const float* __restrict__ faaaa,
                         const float* __restrict__ lnx_w,
                         const float* __restrict__ lnx_b,
                         float* __restrict__ d_out) {
    __shared__ float r_s[HS], k_s[HS], td_s[HS];
    __shared__ float red[HS], red2[HS];
    int h = blockIdx.x;
    int d = threadIdx.x;   // 64
    int base = h * HS;
    float rv = g_rkvg[0][base + d];
    float kv = g_rkvg[1][base + d];
    float vv = g_rkvg[2][base + d];
    r_s[d] = rv; k_s[d] = kv; td_s[d] = g_td[base + d];
    // dot1 = sum_k r*k*faaaa
    red[d] = rv * kv * faaaa[base + d];
    __syncthreads();
    for (int s = 32; s > 0; s >>= 1) {
        if (d < s) red[d] += red[d + s];
        __syncthreads();
    }
    float dot1 = red[0];
    // acc = sum_k r[k]*s2[k][d];  s2out[k][d] = k[k]*v[d] + s2[k][d]*td[k]
    float acc = 0.f;
    const float* s2 = state2 + (size_t)h * HS * HS;
    float* s2o = d_out + 2 * H + (size_t)h * HS * HS;
#pragma unroll 4
    for (int kk = 0; kk < HS; kk++) {
        float s2v = s2[kk * HS + d];
        acc += r_s[kk] * s2v;
        s2o[kk * HS + d] = k_s[kk] * vv + s2v * td_s[kk];
    }
    float out_d = vv * dot1 + acc;
    // instance norm over 64
    __syncthreads();
    red[d] = out_d; red2[d] = out_d * out_d;
    __syncthreads();
    for (int s = 32; s > 0; s >>= 1) {
        if (d < s) { red[d] += red[d + s]; red2[d] += red2[d + s]; }
        __syncthreads();
    }
    float mean = red[0] * (1.0f / HS);
    float var = red2[0] * (1.0f / HS) - mean * mean;
    float o = (out_d - mean) * rsqrtf(var + 1e-5f) * lnx_w[base + d] + lnx_b[base + d];
    g_gx[base + d] = o * g_rkvg[3][base + d];
}

// ---------------- K8a: Wo split-K partials ----------------
// grid: (64 splits, 4 col-chunks), 256 threads.
__global__ void k8a_wo_part(const float* __restrict__ Wo) {
    __shared__ float sv[64];
    int split = blockIdx.x;   // 64
    int cc = blockIdx.y;      // 4 column chunks
    int t = threadIdx.x;      // 256
    if (t < 64) sv[t] = g_gx[split * 64 + t];
    __syncthreads();
    const float4* W4 = reinterpret_cast<const float4*>(Wo);
    int col = cc * 256 + t;
    float4 acc = make_float4(0.f, 0.f, 0.f, 0.f);
#pragma unroll 4
    for (int i = 0; i < 64; i++) {
        float m = sv[i];
        float4 w = W4[(size_t)(split * 64 + i) * 1024 + col];
        acc.x += m * w.x; acc.y += m * w.y; acc.z += m * w.z; acc.w += m * w.w;
    }
    reinterpret_cast<float4*>(&g_wo_part[(size_t)split * H])[col] = acc;
}

// ---------------- K8b: reduce + residual ----------------
__global__ void k8b_final(const float* __restrict__ x, float* __restrict__ d_out) {
    int j = blockIdx.x * 256 + threadIdx.x;
    float a = 0.f;
#pragma unroll 8
    for (int s = 0; s < 64; s++) a += g_wo_part[(size_t)s * H + j];
    d_out[j] = x[j] + a;
}

extern "C" void kernel_launch(void* const* d_in, const int* in_sizes, int n_in,
                              void* d_out, int out_size) {
    const float* x      = (const float*)d_in[0];
    const float* state1 = (const float*)d_in[1];
    const float* state2 = (const float*)d_in[2];
    const float* ln1_w  = (const float*)d_in[3];
    const float* ln1_b  = (const float*)d_in[4];
    const float* tmx    = (const float*)d_in[5];
    const float* tmw    = (const float*)d_in[6];
    const float* tmk    = (const float*)d_in[7];
    const float* tmv    = (const float*)d_in[8];
    const float* tmr    = (const float*)d_in[9];
    const float* tmg    = (const float*)d_in[10];
    const float* Wmaa1  = (const float*)d_in[11];
    const float* Wmaa2  = (const float*)d_in[12];
    const float* tdec   = (const float*)d_in[13];
    const float* Wd1    = (const float*)d_in[14];
    const float* Wd2    = (const float*)d_in[15];
    const float* faaaa  = (const float*)d_in[16];
    const float* Wr     = (const float*)d_in[17];
    const float* Wk     = (const float*)d_in[18];
    const float* Wv     = (const float*)d_in[19];
    const float* Wg     = (const float*)d_in[20];
    const float* Wo     = (const float*)d_in[21];
    const float* lnxw   = (const float*)d_in[22];
    const float* lnxb   = (const float*)d_in[23];
    float* out = (float*)d_out;

    k1_ln_prep<<<1, 1024>>>(x, state1, ln1_w, ln1_b, tmx, out);
    k2_maa1_part<<<16, 320>>>(Wmaa1);
    k3_mix<<<dim3(16, 5), 256>>>(Wmaa2, tmw, tmk, tmv, tmr, tmg);
    k4_big_part<<<dim3(64, 4, 4), 256>>>(Wr, Wk, Wv, Wg);
    k4b_wd1_part<<<16, 128>>>(Wd1);
    k5_reduce<<<64, 256>>>();
    k5b_ddpre<<<1, 128>>>();
    k6_decay<<<16, 256>>>(Wd2, tdec);
    k7_heads<<<64, 64>>>(state2, faaaa, lnxw, lnxb, out);
    k8a_wo_part<<<dim3(64, 4), 256>>>(Wo);
    k8b_final<<<16, 256>>>(x, out);
}

// round 4
// speedup vs baseline: 1.2719x; 1.2719x over previous
#include <cuda_runtime.h>
#include <math.h>

#define H 4096
#define HS 64
#define NH 64
#define TM 64
#define TD 128

// ---------------- scratch (device globals) ----------------
__device__ float g_xn[H];
__device__ float g_sx[H];
__device__ float g_maa_part[128][5 * TM];     // 128 chunks x 320
__device__ float g_m[5][H];                   // mw, mk, mv, mr, mg
__device__ float g_part[4 * 64 * H];          // split-K partials for Wr/Wk/Wv/Wg
__device__ float g_wd1_part[64][TD];          // 64 splits x 128
__device__ float g_rkvg[4][H];                // r, k, v, g(silu)
__device__ float g_td[H];
__device__ float g_gx[H];
__device__ float g_wo_part[64 * H];

// ---------------- K2': LN1 (redundant per block) + token shift + maa1 GEMV partials ----
// grid 128 blocks x 320 threads. Block c handles rows [c*32, c*32+32).
// Blocks 0..3 additionally write g_xn/g_sx/state1_out for their 1024-row quarter.
__global__ void k2_ln_maa1(const float* __restrict__ x,
                           const float* __restrict__ s1,
                           const float* __restrict__ ln1_w,
                           const float* __restrict__ ln1_b,
                           const float* __restrict__ tmx,
                           const float* __restrict__ Wmaa1,
                           float* __restrict__ d_out) {
    __shared__ float ssum[320], ssq[320];
    __shared__ float sv[32];
    __shared__ float s_mean, s_rs;
    int t = threadIdx.x;
    int c = blockIdx.x;

    // full-vector LN statistics (redundant per block; x is L2-resident)
    float lsum = 0.f, lsq = 0.f;
    const float4* x4 = reinterpret_cast<const float4*>(x);
    for (int i = t; i < 1024; i += 320) {
        float4 v = x4[i];
        lsum += v.x + v.y + v.z + v.w;
        lsq += v.x * v.x + v.y * v.y + v.z * v.z + v.w * v.w;
    }
    ssum[t] = lsum; ssq[t] = lsq;
    __syncthreads();
    if (t < 64) {
        float a = ssum[t], b = ssq[t];
        for (int i = t + 64; i < 320; i += 64) { a += ssum[i]; b += ssq[i]; }
        ssum[t] = a; ssq[t] = b;
    }
    __syncthreads();
    if (t < 32) { ssum[t] += ssum[t + 32]; ssq[t] += ssq[t + 32]; }
    __syncthreads();
    if (t < 16) { ssum[t] += ssum[t + 16]; ssq[t] += ssq[t + 16]; }
    __syncthreads();
    if (t < 8) { ssum[t] += ssum[t + 8]; ssq[t] += ssq[t + 8]; }
    __syncthreads();
    if (t < 4) { ssum[t] += ssum[t + 4]; ssq[t] += ssq[t + 4]; }
    __syncthreads();
    if (t == 0) {
        float su = ssum[0] + ssum[1] + ssum[2] + ssum[3];
        float sq = ssq[0] + ssq[1] + ssq[2] + ssq[3];
        float mean = su * (1.0f / H);
        float var = sq * (1.0f / H) - mean * mean;
        s_mean = mean;
        s_rs = rsqrtf(var + 1e-5f);
    }
    __syncthreads();
    float mean = s_mean, rs = s_rs;

    // rows for this block's GEMV chunk: compute xxx on the fly
    if (t < 32) {
        int i = c * 32 + t;
        float xn = (x[i] - mean) * rs * ln1_w[i] + ln1_b[i];
        float sx = s1[i] - xn;
        sv[t] = xn + sx * tmx[i];
    }
    // blocks 0..3: write g_xn / g_sx / state1_out for quarter
    if (c < 4) {
        for (int j = t; j < 1024; j += 320) {
            int i = c * 1024 + j;
            float xn = (x[i] - mean) * rs * ln1_w[i] + ln1_b[i];
            float sx = s1[i] - xn;
            g_xn[i] = xn;
            g_sx[i] = sx;
            d_out[H + i] = xn;      // state1_out
        }
    }
    __syncthreads();

    float acc = 0.f;
#pragma unroll 8
    for (int i = 0; i < 32; i++)
        acc += sv[i] * Wmaa1[(size_t)(c * 32 + i) * 320 + t];
    g_maa_part[c][t] = acc;
}

// ---------------- K3: mix = tanh(reduce), m = xn + sx*(mix@W_maa2 + maa) ----------------
__global__ void k3_mix(const float* __restrict__ Wmaa2,
                       const float* __restrict__ maa_w,
                       const float* __restrict__ maa_k,
                       const float* __restrict__ maa_v,
                       const float* __restrict__ maa_r,
                       const float* __restrict__ maa_g) {
    __shared__ float mixs[TM];
    int s = blockIdx.y;
    int t = threadIdx.x;
    if (t < TM) {
        float a = 0.f;
#pragma unroll 8
        for (int cc = 0; cc < 128; cc++) a += g_maa_part[cc][s * TM + t];
        mixs[t] = tanhf(a);
    }
    __syncthreads();
    int h = blockIdx.x * 256 + t;
    float acc = 0.f;
#pragma unroll 8
    for (int e = 0; e < TM; e++)
        acc += mixs[e] * Wmaa2[(size_t)(s * TM + e) * H + h];
    const float* maa = (s == 0) ? maa_w : (s == 1) ? maa_k : (s == 2) ? maa_v
                      : (s == 3) ? maa_r : maa_g;
    g_m[s][h] = g_xn[h] + g_sx[h] * (acc + maa[h]);
}

// ---------------- K4: split-K GEMV partials for Wr/Wk/Wv/Wg + Wd1 ----------------
// grid (64 splits, 5 mats, 2 halves), 256 threads.
// mats 0..3: each thread 2 float4 columns (col and col+256) of its 512-col half.
// mat 4 (Wd1, z==0 only): threads 0..127 over 128 cols.
__global__ void k4_big(const float* __restrict__ Wr,
                       const float* __restrict__ Wk,
                       const float* __restrict__ Wv,
                       const float* __restrict__ Wg,
                       const float* __restrict__ Wd1) {
    __shared__ float sv[64];
    int split = blockIdx.x;
    int mat = blockIdx.y;
    int z = blockIdx.z;
    int t = threadIdx.x;
    if (mat == 4 && z == 1) return;      // uniform per block

    const float* vec = (mat == 0) ? g_m[3] : (mat == 1) ? g_m[1]
                      : (mat == 2) ? g_m[2] : (mat == 3) ? g_m[4] : g_m[0];
    if (t < 64) sv[t] = vec[split * 64 + t];
    __syncthreads();

    if (mat < 4) {
        const float* W = (mat == 0) ? Wr : (mat == 1) ? Wk : (mat == 2) ? Wv : Wg;
        const float4* W4 = reinterpret_cast<const float4*>(W);
        int col0 = z * 512 + t;          // float4 col
        int col1 = col0 + 256;
        float4 a0 = make_float4(0.f, 0.f, 0.f, 0.f);
        float4 a1 = make_float4(0.f, 0.f, 0.f, 0.f);
#pragma unroll 4
        for (int i = 0; i < 64; i++) {
            float m = sv[i];
            size_t rb = (size_t)(split * 64 + i) * 1024;
            float4 w0 = W4[rb + col0];
            float4 w1 = W4[rb + col1];
            a0.x += m * w0.x; a0.y += m * w0.y; a0.z += m * w0.z; a0.w += m * w0.w;
            a1.x += m * w1.x; a1.y += m * w1.y; a1.z += m * w1.z; a1.w += m * w1.w;
        }
        float4* P = reinterpret_cast<float4*>(&g_part[(size_t)(mat * 64 + split) * H]);
        P[col0] = a0;
        P[col1] = a1;
    } else {
        if (t < TD) {
            float acc = 0.f;
#pragma unroll 4
            for (int i = 0; i < 64; i++)
                acc += sv[i] * Wd1[(size_t)(split * 64 + i) * TD + t];
            g_wd1_part[split][t] = acc;
        }
    }
}

// ---------------- K_mid: rkvg reduce (+silu) AND decay (wd1 reduce + tanh + Wd2 + td) ----
// grid 80 blocks x 256 threads. b<64: rkvg reduce; b>=64: decay for 256-col stripe.
__global__ void k_mid(const float* __restrict__ Wd2,
                      const float* __restrict__ time_decay) {
    int b = blockIdx.x;
    int t = threadIdx.x;
    if (b < 64) {
        int idx = b * 256 + t;
        int mat = idx >> 12;
        int j = idx & (H - 1);
        float a = 0.f;
#pragma unroll 8
        for (int s = 0; s < 64; s++)
            a += g_part[(size_t)(mat * 64 + s) * H + j];
        if (mat == 3) a = a / (1.0f + expf(-a));   // silu
        g_rkvg[mat][j] = a;
    } else {
        __shared__ float sdd[TD];
        if (t < TD) {
            float a = 0.f;
#pragma unroll 8
            for (int s = 0; s < 64; s++) a += g_wd1_part[s][t];
            sdd[t] = tanhf(a);
        }
        __syncthreads();
        int j = (b - 64) * 256 + t;
        float acc = 0.f;
#pragma unroll 8
        for (int e = 0; e < TD; e++)
            acc += sdd[e] * Wd2[(size_t)e * H + j];
        g_td[j] = expf(-expf(time_decay[j] + acc));
    }
}

// ---------------- K7: per-head attention + state update + instnorm + gate ----------------
// 64 blocks x 256 threads. d = t&63, q = t>>6 handles kk in [16q,16q+16).
__global__ void k7_heads(const float* __restrict__ state2,
                         const float* __restrict__ faaaa,
                         const float* __restrict__ lnx_w,
                         const float* __restrict__ lnx_b,
                         float* __restrict__ d_out) {
    __shared__ float r_s[HS], k_s[HS], v_s[HS], td_s[HS];
    __shared__ float prod[HS], part[4 * HS], red[HS], red2[HS];
    int h = blockIdx.x;
    int t = threadIdx.x;
    int d = t & 63;
    int q = t >> 6;
    int base = h * HS;

    if (t < 64) {
        float rv = g_rkvg[0][base + t];
        float kv = g_rkvg[1][base + t];
        r_s[t] = rv;
        k_s[t] = kv;
        v_s[t] = g_rkvg[2][base + t];
        td_s[t] = g_td[base + t];
        prod[t] = rv * kv * faaaa[base + t];
    }
    __syncthreads();
    if (t < 32) prod[t] += prod[t + 32];
    __syncthreads();
    if (t < 16) prod[t] += prod[t + 16];
    __syncthreads();
    if (t < 8) prod[t] += prod[t + 8];
    __syncthreads();
    if (t < 4) prod[t] += prod[t + 4];
    __syncthreads();
    if (t < 2) prod[t] += prod[t + 2];
    __syncthreads();
    if (t == 0) prod[0] += prod[1];
    __syncthreads();
    float dot1 = prod[0];

    const float* s2 = state2 + (size_t)h * HS * HS;
    float* s2o = d_out + 2 * H + (size_t)h * HS * HS;
    float vv = v_s[d];
    float acc = 0.f;
#pragma unroll
    for (int kk = q * 16; kk < q * 16 + 16; kk++) {
        float s2v = s2[kk * HS + d];
        acc += r_s[kk] * s2v;
        s2o[kk * HS + d] = k_s[kk] * vv + s2v * td_s[kk];
    }
    part[q * HS + d] = acc;
    __syncthreads();

    if (t < 64) {
        float out_d = v_s[t] * dot1 + part[t] + part[HS + t] + part[2 * HS + t] + part[3 * HS + t];
        red[t] = out_d;
        red2[t] = out_d * out_d;
        part[t] = out_d;   // stash for after reduction
    }
    __syncthreads();
    if (t < 32) { red[t] += red[t + 32]; red2[t] += red2[t + 32]; }
    __syncthreads();
    if (t < 16) { red[t] += red[t + 16]; red2[t] += red2[t + 16]; }
    __syncthreads();
    if (t < 8) { red[t] += red[t + 8]; red2[t] += red2[t + 8]; }
    __syncthreads();
    if (t < 4) { red[t] += red[t + 4]; red2[t] += red2[t + 4]; }
    __syncthreads();
    if (t < 2) { red[t] += red[t + 2]; red2[t] += red2[t + 2]; }
    __syncthreads();
    if (t == 0) { red[0] += red[1]; red2[0] += red2[1]; }
    __syncthreads();
    if (t < 64) {
        float mean = red[0] * (1.0f / HS);
        float var = red2[0] * (1.0f / HS) - mean * mean;
        float o = (part[t] - mean) * rsqrtf(var + 1e-5f) * lnx_w[base + t] + lnx_b[base + t];
        g_gx[base + t] = o * g_rkvg[3][base + t];
    }
}

// ---------------- K8a: Wo split-K partials ----------------
// grid (64 splits, 2 halves), 256 threads, 2 float4 cols per thread.
__global__ void k8a_wo_part(const float* __restrict__ Wo) {
    __shared__ float sv[64];
    int split = blockIdx.x;
    int z = blockIdx.y;
    int t = threadIdx.x;
    if (t < 64) sv[t] = g_gx[split * 64 + t];
    __syncthreads();
    const float4* W4 = reinterpret_cast<const float4*>(Wo);
    int col0 = z * 512 + t;
    int col1 = col0 + 256;
    float4 a0 = make_float4(0.f, 0.f, 0.f, 0.f);
    float4 a1 = make_float4(0.f, 0.f, 0.f, 0.f);
#pragma unroll 4
    for (int i = 0; i < 64; i++) {
        float m = sv[i];
        size_t rb = (size_t)(split * 64 + i) * 1024;
        float4 w0 = W4[rb + col0];
        float4 w1 = W4[rb + col1];
        a0.x += m * w0.x; a0.y += m * w0.y; a0.z += m * w0.z; a0.w += m * w0.w;
        a1.x += m * w1.x; a1.y += m * w1.y; a1.z += m * w1.z; a1.w += m * w1.w;
    }
    float4* P = reinterpret_cast<float4*>(&g_wo_part[(size_t)split * H]);
    P[col0] = a0;
    P[col1] = a1;
}

// ---------------- K8b: reduce + residual ----------------
__global__ void k8b_final(const float* __restrict__ x, float* __restrict__ d_out) {
    int j = blockIdx.x * 256 + threadIdx.x;
    float a = 0.f;
#pragma unroll 8
    for (int s = 0; s < 64; s++) a += g_wo_part[(size_t)s * H + j];
    d_out[j] = x[j] + a;
}

extern "C" void kernel_launch(void* const* d_in, const int* in_sizes, int n_in,
                              void* d_out, int out_size) {
    const float* x      = (const float*)d_in[0];
    const float* state1 = (const float*)d_in[1];
    const float* state2 = (const float*)d_in[2];
    const float* ln1_w  = (const float*)d_in[3];
    const float* ln1_b  = (const float*)d_in[4];
    const float* tmx    = (const float*)d_in[5];
    const float* tmw    = (const float*)d_in[6];
    const float* tmk    = (const float*)d_in[7];
    const float* tmv    = (const float*)d_in[8];
    const float* tmr    = (const float*)d_in[9];
    const float* tmg    = (const float*)d_in[10];
    const float* Wmaa1  = (const float*)d_in[11];
    const float* Wmaa2  = (const float*)d_in[12];
    const float* tdec   = (const float*)d_in[13];
    const float* Wd1    = (const float*)d_in[14];
    const float* Wd2    = (const float*)d_in[15];
    const float* faaaa  = (const float*)d_in[16];
    const float* Wr     = (const float*)d_in[17];
    const float* Wk     = (const float*)d_in[18];
    const float* Wv     = (const float*)d_in[19];
    const float* Wg     = (const float*)d_in[20];
    const float* Wo     = (const float*)d_in[21];
    const float* lnxw   = (const float*)d_in[22];
    const float* lnxb   = (const float*)d_in[23];
    float* out = (float*)d_out;

    k2_ln_maa1<<<128, 320>>>(x, state1, ln1_w, ln1_b, tmx, Wmaa1, out);
    k3_mix<<<dim3(16, 5), 256>>>(Wmaa2, tmw, tmk, tmv, tmr, tmg);
    k4_big<<<dim3(64, 5, 2), 256>>>(Wr, Wk, Wv, Wg, Wd1);
    k_mid<<<80, 256>>>(Wd2, tdec);
    k7_heads<<<64, 256>>>(state2, faaaa, lnxw, lnxb, out);
    k8a_wo_part<<<dim3(64, 2), 256>>>(Wo);
    k8b_final<<<16, 256>>>(x, out);
}

// round 5
// speedup vs baseline: 1.3671x; 1.0749x over previous
#include <cuda_runtime.h>
#include <math.h>

#define H 4096
#define HS 64
#define NH 64
#define TM 64
#define TD 128

// ---------------- scratch (device globals) ----------------
__device__ float g_xn[H];
__device__ float g_sx[H];
__device__ float g_maa_part[128][5 * TM];     // 128 chunks x 320
__device__ float g_m[5][H];                   // mw, mk, mv, mr, mg
__device__ float g_part[4 * 64 * H];          // split-K partials for Wr/Wk/Wv/Wg
__device__ float g_wd1_part[64][TD];          // 64 splits x 128
__device__ float g_rkvg[4][H];                // r, k, v, g(silu)
__device__ float g_td[H];
__device__ float g_gx[H];
__device__ float g_wo_part[64 * H];

// ---------------- K2: LN1 (redundant per block) + token shift + maa1 GEMV partials ----
__global__ void k2_ln_maa1(const float* __restrict__ x,
                           const float* __restrict__ s1,
                           const float* __restrict__ ln1_w,
                           const float* __restrict__ ln1_b,
                           const float* __restrict__ tmx,
                           const float* __restrict__ Wmaa1,
                           float* __restrict__ d_out) {
    __shared__ float ssum[320], ssq[320];
    __shared__ float sv[32];
    __shared__ float s_mean, s_rs;
    int t = threadIdx.x;
    int c = blockIdx.x;

    float lsum = 0.f, lsq = 0.f;
    const float4* x4 = reinterpret_cast<const float4*>(x);
    for (int i = t; i < 1024; i += 320) {
        float4 v = x4[i];
        lsum += v.x + v.y + v.z + v.w;
        lsq += v.x * v.x + v.y * v.y + v.z * v.z + v.w * v.w;
    }
    ssum[t] = lsum; ssq[t] = lsq;
    __syncthreads();
    if (t < 64) {
        float a = ssum[t], b = ssq[t];
        for (int i = t + 64; i < 320; i += 64) { a += ssum[i]; b += ssq[i]; }
        ssum[t] = a; ssq[t] = b;
    }
    __syncthreads();
    if (t < 32) { ssum[t] += ssum[t + 32]; ssq[t] += ssq[t + 32]; }
    __syncthreads();
    if (t < 16) { ssum[t] += ssum[t + 16]; ssq[t] += ssq[t + 16]; }
    __syncthreads();
    if (t < 8) { ssum[t] += ssum[t + 8]; ssq[t] += ssq[t + 8]; }
    __syncthreads();
    if (t < 4) { ssum[t] += ssum[t + 4]; ssq[t] += ssq[t + 4]; }
    __syncthreads();
    if (t == 0) {
        float su = ssum[0] + ssum[1] + ssum[2] + ssum[3];
        float sq = ssq[0] + ssq[1] + ssq[2] + ssq[3];
        float mean = su * (1.0f / H);
        float var = sq * (1.0f / H) - mean * mean;
        s_mean = mean;
        s_rs = rsqrtf(var + 1e-5f);
    }
    __syncthreads();
    float mean = s_mean, rs = s_rs;

    if (t < 32) {
        int i = c * 32 + t;
        float xn = (x[i] - mean) * rs * ln1_w[i] + ln1_b[i];
        float sx = s1[i] - xn;
        sv[t] = xn + sx * tmx[i];
    }
    if (c < 4) {
        for (int j = t; j < 1024; j += 320) {
            int i = c * 1024 + j;
            float xn = (x[i] - mean) * rs * ln1_w[i] + ln1_b[i];
            float sx = s1[i] - xn;
            g_xn[i] = xn;
            g_sx[i] = sx;
            d_out[H + i] = xn;      // state1_out
        }
    }
    __syncthreads();

    float acc = 0.f;
#pragma unroll 8
    for (int i = 0; i < 32; i++)
        acc += sv[i] * Wmaa1[(size_t)(c * 32 + i) * 320 + t];
    g_maa_part[c][t] = acc;
}

// ---------------- K3: mix = tanh(reduce), m = xn + sx*(mix@W_maa2 + maa) ----------------
__global__ void k3_mix(const float* __restrict__ Wmaa2,
                       const float* __restrict__ maa_w,
                       const float* __restrict__ maa_k,
                       const float* __restrict__ maa_v,
                       const float* __restrict__ maa_r,
                       const float* __restrict__ maa_g) {
    __shared__ float mixs[TM];
    int s = blockIdx.y;
    int t = threadIdx.x;
    if (t < TM) {
        float a = 0.f;
#pragma unroll 8
        for (int cc = 0; cc < 128; cc++) a += g_maa_part[cc][s * TM + t];
        mixs[t] = tanhf(a);
    }
    __syncthreads();
    int h = blockIdx.x * 256 + t;
    float acc = 0.f;
#pragma unroll 8
    for (int e = 0; e < TM; e++)
        acc += mixs[e] * Wmaa2[(size_t)(s * TM + e) * H + h];
    const float* maa = (s == 0) ? maa_w : (s == 1) ? maa_k : (s == 2) ? maa_v
                      : (s == 3) ? maa_r : maa_g;
    g_m[s][h] = g_xn[h] + g_sx[h] * (acc + maa[h]);
}

// ---------------- K4: split-K GEMV partials for Wr/Wk/Wv/Wg + Wd1 ----------------
// grid (64 splits, 5 mats), 256 threads.
// mats 0..3: each thread 4 independent float4 columns (t, t+256, t+512, t+768).
// mat 4: Wd1, threads 0..127.
__global__ void k4_big(const float* __restrict__ Wr,
                       const float* __restrict__ Wk,
                       const float* __restrict__ Wv,
                       const float* __restrict__ Wg,
                       const float* __restrict__ Wd1) {
    __shared__ float sv[64];
    int split = blockIdx.x;
    int mat = blockIdx.y;
    int t = threadIdx.x;

    const float* vec = (mat == 0) ? g_m[3] : (mat == 1) ? g_m[1]
                      : (mat == 2) ? g_m[2] : (mat == 3) ? g_m[4] : g_m[0];
    if (t < 64) sv[t] = vec[split * 64 + t];
    __syncthreads();

    if (mat < 4) {
        const float* W = (mat == 0) ? Wr : (mat == 1) ? Wk : (mat == 2) ? Wv : Wg;
        const float4* W4 = reinterpret_cast<const float4*>(W);
        float4 a0 = make_float4(0.f, 0.f, 0.f, 0.f);
        float4 a1 = make_float4(0.f, 0.f, 0.f, 0.f);
        float4 a2 = make_float4(0.f, 0.f, 0.f, 0.f);
        float4 a3 = make_float4(0.f, 0.f, 0.f, 0.f);
#pragma unroll 4
        for (int i = 0; i < 64; i++) {
            float m = sv[i];
            size_t rb = (size_t)(split * 64 + i) * 1024;
            float4 w0 = W4[rb + t];
            float4 w1 = W4[rb + t + 256];
            float4 w2 = W4[rb + t + 512];
            float4 w3 = W4[rb + t + 768];
            a0.x += m * w0.x; a0.y += m * w0.y; a0.z += m * w0.z; a0.w += m * w0.w;
            a1.x += m * w1.x; a1.y += m * w1.y; a1.z += m * w1.z; a1.w += m * w1.w;
            a2.x += m * w2.x; a2.y += m * w2.y; a2.z += m * w2.z; a2.w += m * w2.w;
            a3.x += m * w3.x; a3.y += m * w3.y; a3.z += m * w3.z; a3.w += m * w3.w;
        }
        float4* P = reinterpret_cast<float4*>(&g_part[(size_t)(mat * 64 + split) * H]);
        P[t] = a0;
        P[t + 256] = a1;
        P[t + 512] = a2;
        P[t + 768] = a3;
    } else {
        if (t < TD) {
            float acc = 0.f;
#pragma unroll 8
            for (int i = 0; i < 64; i++)
                acc += sv[i] * Wd1[(size_t)(split * 64 + i) * TD + t];
            g_wd1_part[split][t] = acc;
        }
    }
}

// ---------------- K_mid: rkvg reduce (+silu) AND decay path ----------------
// grid 160 blocks x 256 threads.
// b<128: reduce. Block covers 128 outputs; 2 threads/output, each sums 32 splits.
// b>=128: decay. 32 blocks; block covers 128 cols; 2 threads/col, each sums 64 Wd2 rows.
__global__ void k_mid(const float* __restrict__ Wd2,
                      const float* __restrict__ time_decay) {
    __shared__ float sred[256];
    int b = blockIdx.x;
    int t = threadIdx.x;
    int lo = t & 127;
    int half = t >> 7;
    if (b < 128) {
        int idx = b * 128 + lo;        // 0..16383
        int mat = idx >> 12;
        int j = idx & (H - 1);
        float a = 0.f;
        const float* P = &g_part[(size_t)mat * 64 * H + j];
#pragma unroll 8
        for (int s = half * 32; s < half * 32 + 32; s++)
            a += P[(size_t)s * H];
        sred[t] = a;
        __syncthreads();
        if (t < 128) {
            float v = sred[t] + sred[t + 128];
            if (mat == 3) v = v / (1.0f + expf(-v));   // silu
            g_rkvg[mat][j] = v;
        }
    } else {
        __shared__ float sdd[TD];
        if (t < TD) {
            float a = 0.f;
#pragma unroll 8
            for (int s = 0; s < 64; s++) a += g_wd1_part[s][t];
            sdd[t] = tanhf(a);
        }
        __syncthreads();
        int col = (b - 128) * 128 + lo;
        float acc = 0.f;
#pragma unroll 8
        for (int e = half * 64; e < half * 64 + 64; e++)
            acc += sdd[e] * Wd2[(size_t)e * H + col];
        sred[t] = acc;
        __syncthreads();
        if (t < 128) {
            float v = sred[t] + sred[t + 128];
            g_td[col] = expf(-expf(time_decay[col] + v));
        }
    }
}

// ---------------- K7: per-head attention + state update + instnorm + gate ----------------
__global__ void k7_heads(const float* __restrict__ state2,
                         const float* __restrict__ faaaa,
                         const float* __restrict__ lnx_w,
                         const float* __restrict__ lnx_b,
                         float* __restrict__ d_out) {
    __shared__ float r_s[HS], k_s[HS], v_s[HS], td_s[HS];
    __shared__ float prod[HS], part[4 * HS], red[HS], red2[HS];
    int h = blockIdx.x;
    int t = threadIdx.x;
    int d = t & 63;
    int q = t >> 6;
    int base = h * HS;

    if (t < 64) {
        float rv = g_rkvg[0][base + t];
        float kv = g_rkvg[1][base + t];
        r_s[t] = rv;
        k_s[t] = kv;
        v_s[t] = g_rkvg[2][base + t];
        td_s[t] = g_td[base + t];
        prod[t] = rv * kv * faaaa[base + t];
    }
    __syncthreads();
    if (t < 32) prod[t] += prod[t + 32];
    __syncthreads();
    if (t < 16) prod[t] += prod[t + 16];
    __syncthreads();
    if (t < 8) prod[t] += prod[t + 8];
    __syncthreads();
    if (t < 4) prod[t] += prod[t + 4];
    __syncthreads();
    if (t < 2) prod[t] += prod[t + 2];
    __syncthreads();
    if (t == 0) prod[0] += prod[1];
    __syncthreads();
    float dot1 = prod[0];

    const float* s2 = state2 + (size_t)h * HS * HS;
    float* s2o = d_out + 2 * H + (size_t)h * HS * HS;
    float vv = v_s[d];
    float acc = 0.f;
#pragma unroll
    for (int kk = q * 16; kk < q * 16 + 16; kk++) {
        float s2v = s2[kk * HS + d];
        acc += r_s[kk] * s2v;
        s2o[kk * HS + d] = k_s[kk] * vv + s2v * td_s[kk];
    }
    part[q * HS + d] = acc;
    __syncthreads();

    if (t < 64) {
        float out_d = v_s[t] * dot1 + part[t] + part[HS + t] + part[2 * HS + t] + part[3 * HS + t];
        red[t] = out_d;
        red2[t] = out_d * out_d;
        part[t] = out_d;
    }
    __syncthreads();
    if (t < 32) { red[t] += red[t + 32]; red2[t] += red2[t + 32]; }
    __syncthreads();
    if (t < 16) { red[t] += red[t + 16]; red2[t] += red2[t + 16]; }
    __syncthreads();
    if (t < 8) { red[t] += red[t + 8]; red2[t] += red2[t + 8]; }
    __syncthreads();
    if (t < 4) { red[t] += red[t + 4]; red2[t] += red2[t + 4]; }
    __syncthreads();
    if (t < 2) { red[t] += red[t + 2]; red2[t] += red2[t + 2]; }
    __syncthreads();
    if (t == 0) { red[0] += red[1]; red2[0] += red2[1]; }
    __syncthreads();
    if (t < 64) {
        float mean = red[0] * (1.0f / HS);
        float var = red2[0] * (1.0f / HS) - mean * mean;
        float o = (part[t] - mean) * rsqrtf(var + 1e-5f) * lnx_w[base + t] + lnx_b[base + t];
        g_gx[base + t] = o * g_rkvg[3][base + t];
    }
}

// ---------------- K8a: Wo split-K partials ----------------
// grid (64 splits, 4 cc), 256 threads, 1 float4 col.
__global__ void k8a_wo_part(const float* __restrict__ Wo) {
    __shared__ float sv[64];
    int split = blockIdx.x;
    int cc = blockIdx.y;
    int t = threadIdx.x;
    if (t < 64) sv[t] = g_gx[split * 64 + t];
    __syncthreads();
    const float4* W4 = reinterpret_cast<const float4*>(Wo);
    int col = cc * 256 + t;
    float4 a0 = make_float4(0.f, 0.f, 0.f, 0.f);
#pragma unroll 8
    for (int i = 0; i < 64; i++) {
        float m = sv[i];
        float4 w = W4[(size_t)(split * 64 + i) * 1024 + col];
        a0.x += m * w.x; a0.y += m * w.y; a0.z += m * w.z; a0.w += m * w.w;
    }
    reinterpret_cast<float4*>(&g_wo_part[(size_t)split * H])[col] = a0;
}

// ---------------- K8b: reduce + residual ----------------
// 32 blocks x 256: 2 threads/output, each sums 32 splits.
__global__ void k8b_final(const float* __restrict__ x, float* __restrict__ d_out) {
    __shared__ float sred[256];
    int t = threadIdx.x;
    int lo = t & 127;
    int half = t >> 7;
    int j = blockIdx.x * 128 + lo;
    float a = 0.f;
#pragma unroll 8
    for (int s = half * 32; s < half * 32 + 32; s++)
        a += g_wo_part[(size_t)s * H + j];
    sred[t] = a;
    __syncthreads();
    if (t < 128)
        d_out[j] = x[j] + sred[t] + sred[t + 128];
}

extern "C" void kernel_launch(void* const* d_in, const int* in_sizes, int n_in,
                              void* d_out, int out_size) {
    const float* x      = (const float*)d_in[0];
    const float* state1 = (const float*)d_in[1];
    const float* state2 = (const float*)d_in[2];
    const float* ln1_w  = (const float*)d_in[3];
    const float* ln1_b  = (const float*)d_in[4];
    const float* tmx    = (const float*)d_in[5];
    const float* tmw    = (const float*)d_in[6];
    const float* tmk    = (const float*)d_in[7];
    const float* tmv    = (const float*)d_in[8];
    const float* tmr    = (const float*)d_in[9];
    const float* tmg    = (const float*)d_in[10];
    const float* Wmaa1  = (const float*)d_in[11];
    const float* Wmaa2  = (const float*)d_in[12];
    const float* tdec   = (const float*)d_in[13];
    const float* Wd1    = (const float*)d_in[14];
    const float* Wd2    = (const float*)d_in[15];
    const float* faaaa  = (const float*)d_in[16];
    const float* Wr     = (const float*)d_in[17];
    const float* Wk     = (const float*)d_in[18];
    const float* Wv     = (const float*)d_in[19];
    const float* Wg     = (const float*)d_in[20];
    const float* Wo     = (const float*)d_in[21];
    const float* lnxw   = (const float*)d_in[22];
    const float* lnxb   = (const float*)d_in[23];
    float* out = (float*)d_out;

    k2_ln_maa1<<<128, 320>>>(x, state1, ln1_w, ln1_b, tmx, Wmaa1, out);
    k3_mix<<<dim3(16, 5), 256>>>(Wmaa2, tmw, tmk, tmv, tmr, tmg);
    k4_big<<<dim3(64, 5), 256>>>(Wr, Wk, Wv, Wg, Wd1);
    k_mid<<<160, 256>>>(Wd2, tdec);
    k7_heads<<<64, 256>>>(state2, faaaa, lnxw, lnxb, out);
    k8a_wo_part<<<dim3(64, 4), 256>>>(Wo);
    k8b_final<<<32, 256>>>(x, out);
}